// round 2
// baseline (speedup 1.0000x reference)
#include <cuda_runtime.h>

#define NN 400
#define NC 1000
#define NB 10
#define NE 800
#define XND 121   // 85 cont + 4 shape emb + 32 op emb
#define CF 24
#define DH 128    // 2H
#define H 64
#define CT 128    // configs per tile
#define PADW 132  // padded smem row stride (floats)

typedef unsigned long long ull_t;

// ---- scratch (module-load allocated, no cudaMalloc) ----
__device__ float g_bufA[(size_t)NN * NC * DH];  // 204.8 MB
__device__ float g_bufB[(size_t)NN * NC * DH];  // 204.8 MB
__device__ float g_base[NN * DH];
__device__ int   g_adj[NE];
__device__ int   g_off[NN + 1];
__device__ float g_invdeg[NN];
__device__ float g_invcnt[NB];

// ---- packed f32x2 helpers ----
__device__ __forceinline__ ull_t pk2(float x) {
    ull_t r; asm("mov.b64 %0, {%1, %1};" : "=l"(r) : "f"(x)); return r;
}
__device__ __forceinline__ ull_t fma2(ull_t a, ull_t b, ull_t c) {
    ull_t d; asm("fma.rn.f32x2 %0, %1, %2, %3;" : "=l"(d) : "l"(a), "l"(b), "l"(c)); return d;
}
__device__ __forceinline__ void upk(ull_t a, float& lo, float& hi) {
    asm("mov.b64 {%0, %1}, %2;" : "=f"(lo), "=f"(hi) : "l"(a));
}

// ============================================================
// Setup: CSR by dst, degrees, per-graph node counts. One block.
// ============================================================
__global__ void k_prep(const int* __restrict__ ei, const int* __restrict__ batch) {
    __shared__ int cnt[NN];
    __shared__ int off[NN + 1];
    __shared__ int cur[NN];
    __shared__ int bc[NB];
    int t = threadIdx.x;
    for (int i = t; i < NN; i += blockDim.x) cnt[i] = 0;
    if (t < NB) bc[t] = 0;
    __syncthreads();
    for (int e = t; e < NE; e += blockDim.x) atomicAdd(&cnt[ei[NE + e]], 1);
    for (int i = t; i < NN; i += blockDim.x) atomicAdd(&bc[batch[i]], 1);
    __syncthreads();
    if (t == 0) {
        int s = 0;
        for (int i = 0; i < NN; i++) { off[i] = s; s += cnt[i]; }
        off[NN] = s;
    }
    __syncthreads();
    for (int i = t; i < NN; i += blockDim.x) {
        cur[i] = off[i];
        g_off[i] = off[i];
        g_invdeg[i] = 1.f / fmaxf((float)cnt[i], 1.f);
    }
    if (t == 0) g_off[NN] = off[NN];
    if (t < NB) g_invcnt[t] = 1.f / fmaxf((float)bc[t], 1.f);
    __syncthreads();
    for (int e = t; e < NE; e += blockDim.x) {
        int d = ei[NE + e];
        int p = atomicAdd(&cur[d], 1);
        g_adj[p] = ei[e];
    }
}

// ============================================================
// Per-node config-invariant part of layer 1:
// base[n][f] = b1[f] + xn[n] @ W1[0:121]
// ============================================================
__global__ void k_base(const float* __restrict__ node_feat, const int* __restrict__ opcode,
                       const float* __restrict__ op_emb, const float* __restrict__ shape_emb,
                       const float* __restrict__ W1, const float* __restrict__ b1) {
    __shared__ float xns[XND];
    int n = blockIdx.x, t = threadIdx.x;
    if (t < XND) {
        float v;
        if (t < 85) v = node_feat[n * 86 + t];
        else if (t < 89) { int st = (int)node_feat[n * 86 + 85]; v = shape_emb[st * 4 + (t - 85)]; }
        else v = op_emb[opcode[n] * 32 + (t - 89)];
        xns[t] = v;
    }
    __syncthreads();
    float acc = b1[t];
    #pragma unroll 11
    for (int k = 0; k < XND; k++) acc += xns[k] * W1[k * DH + t];
    g_base[n * DH + t] = acc;
}

// ============================================================
// Fused MLP: x1 = relu(base + cfg @ W1[121:145]); x2 = relu(x1 @ W2 + b2)
// -> g_bufA [n][c][128]
// ============================================================
__global__ void __launch_bounds__(256, 1)
k_mlp(const float* __restrict__ cfgf, const int* __restrict__ batch,
      const float* __restrict__ W1, const float* __restrict__ W2, const float* __restrict__ b2) {
    extern __shared__ float sm[];
    float* sb   = sm;                   // 128
    float* w1t  = sm + DH;              // 24*128
    float* cfgT = w1t + CF * DH;        // 24*132 (transposed [j][c])
    float* x1T  = cfgT + CF * PADW;     // 128*132 (transposed [k][c])
    float* w2s  = x1T + DH * PADW;      // 128*128

    const int n = blockIdx.y;
    const int c0 = blockIdx.x * CT;
    const int span = min(CT, NC - c0);
    const int t = threadIdx.x;

    if (t < DH) sb[t] = g_base[n * DH + t];
    for (int e = t; e < CF * DH; e += 256) w1t[e] = W1[XND * DH + e];
    for (int e = t; e < DH * DH; e += 256) w2s[e] = W2[e];
    const int bn = batch[n];
    const float* cb_ = cfgf + ((size_t)bn * NC + c0) * CF;
    for (int e = t; e < CF * CT; e += 256) {
        int c = e / CF, j = e - c * CF;
        cfgT[j * PADW + c] = (c < span) ? cb_[e] : 0.f;
    }
    __syncthreads();

    const int f = t & 127, g = t >> 7;
    const ull_t bb1 = pk2(sb[f]);

    // Stage 1: 24-deep GEMM, store transposed to smem
    #pragma unroll
    for (int p0 = g * 4; p0 < 64; p0 += 8) {
        ull_t a0 = bb1, a1 = bb1, a2 = bb1, a3 = bb1;
        const int cb = 2 * p0;
        #pragma unroll
        for (int j = 0; j < CF; j++) {
            ull_t w = pk2(w1t[j * DH + f]);
            const ulonglong2* xr = (const ulonglong2*)(cfgT + j * PADW + cb);
            ulonglong2 xA = xr[0], xB = xr[1];
            a0 = fma2(xA.x, w, a0); a1 = fma2(xA.y, w, a1);
            a2 = fma2(xB.x, w, a2); a3 = fma2(xB.y, w, a3);
        }
        float lo, hi;
        float* xrow = x1T + f * PADW + cb;
        upk(a0, lo, hi); xrow[0] = fmaxf(lo, 0.f); xrow[1] = fmaxf(hi, 0.f);
        upk(a1, lo, hi); xrow[2] = fmaxf(lo, 0.f); xrow[3] = fmaxf(hi, 0.f);
        upk(a2, lo, hi); xrow[4] = fmaxf(lo, 0.f); xrow[5] = fmaxf(hi, 0.f);
        upk(a3, lo, hi); xrow[6] = fmaxf(lo, 0.f); xrow[7] = fmaxf(hi, 0.f);
    }
    __syncthreads();

    // Stage 2: 128-deep GEMM -> global
    float* outg = g_bufA + ((size_t)n * NC + c0) * DH;
    const ull_t bb2 = pk2(b2[f]);
    #pragma unroll
    for (int p0 = g * 4; p0 < 64; p0 += 8) {
        ull_t a0 = bb2, a1 = bb2, a2 = bb2, a3 = bb2;
        const int cb = 2 * p0;
        #pragma unroll 16
        for (int k = 0; k < DH; k++) {
            ull_t w = pk2(w2s[k * DH + f]);
            const ulonglong2* xr = (const ulonglong2*)(x1T + k * PADW + cb);
            ulonglong2 xA = xr[0], xB = xr[1];
            a0 = fma2(xA.x, w, a0); a1 = fma2(xA.y, w, a1);
            a2 = fma2(xB.x, w, a2); a3 = fma2(xB.y, w, a3);
        }
        float lo, hi;
        upk(a0, lo, hi);
        if (cb     < span) outg[(size_t)(cb    ) * DH + f] = fmaxf(lo, 0.f);
        if (cb + 1 < span) outg[(size_t)(cb + 1) * DH + f] = fmaxf(hi, 0.f);
        upk(a1, lo, hi);
        if (cb + 2 < span) outg[(size_t)(cb + 2) * DH + f] = fmaxf(lo, 0.f);
        if (cb + 3 < span) outg[(size_t)(cb + 3) * DH + f] = fmaxf(hi, 0.f);
        upk(a2, lo, hi);
        if (cb + 4 < span) outg[(size_t)(cb + 4) * DH + f] = fmaxf(lo, 0.f);
        if (cb + 5 < span) outg[(size_t)(cb + 5) * DH + f] = fmaxf(hi, 0.f);
        upk(a3, lo, hi);
        if (cb + 6 < span) outg[(size_t)(cb + 6) * DH + f] = fmaxf(lo, 0.f);
        if (cb + 7 < span) outg[(size_t)(cb + 7) * DH + f] = fmaxf(hi, 0.f);
    }
}

// ============================================================
// SAGE projection: y[n][c][0:64] = x@Wl + bg (pre-relu),
//                  y[n][c][64:128] = x@Wr.  Reads g_bufA, writes g_bufB.
// ============================================================
template<int D>
__global__ void __launch_bounds__(256, 1)
k_sageG(const float* __restrict__ Wl, const float* __restrict__ Wr, const float* __restrict__ bg) {
    extern __shared__ float sm[];
    float* xT = sm;               // D*PADW
    float* ws = xT + D * PADW;    // D*128 (Wl | Wr interleaved on f)
    float* bs = ws + D * DH;      // 64
    const int n = blockIdx.y, c0 = blockIdx.x * CT;
    const int span = min(CT, NC - c0);
    const int t = threadIdx.x;

    if (t < H) bs[t] = bg[t];
    for (int e = t; e < D * H; e += 256) {
        int k = e / H, f = e - k * H;
        ws[k * DH + f]     = Wl[e];
        ws[k * DH + H + f] = Wr[e];
    }
    const float* xb = g_bufA + ((size_t)n * NC + c0) * D;
    for (int e = t; e < D * CT; e += 256) {
        int c = e / D, k = e - c * D;
        xT[k * PADW + c] = (c < span) ? xb[e] : 0.f;
    }
    __syncthreads();

    const int f = t & 127, g = t >> 7;
    const ull_t bb = pk2(f < H ? bs[f] : 0.f);
    float* yb = g_bufB + ((size_t)n * NC + c0) * DH;
    #pragma unroll
    for (int p0 = g * 4; p0 < 64; p0 += 8) {
        ull_t a0 = bb, a1 = bb, a2 = bb, a3 = bb;
        const int cb = 2 * p0;
        #pragma unroll 16
        for (int k = 0; k < D; k++) {
            ull_t w = pk2(ws[k * DH + f]);
            const ulonglong2* xr = (const ulonglong2*)(xT + k * PADW + cb);
            ulonglong2 xA = xr[0], xB = xr[1];
            a0 = fma2(xA.x, w, a0); a1 = fma2(xA.y, w, a1);
            a2 = fma2(xB.x, w, a2); a3 = fma2(xB.y, w, a3);
        }
        float lo, hi;
        upk(a0, lo, hi);
        if (cb     < span) yb[(size_t)(cb    ) * DH + f] = lo;
        if (cb + 1 < span) yb[(size_t)(cb + 1) * DH + f] = hi;
        upk(a1, lo, hi);
        if (cb + 2 < span) yb[(size_t)(cb + 2) * DH + f] = lo;
        if (cb + 3 < span) yb[(size_t)(cb + 3) * DH + f] = hi;
        upk(a2, lo, hi);
        if (cb + 4 < span) yb[(size_t)(cb + 4) * DH + f] = lo;
        if (cb + 5 < span) yb[(size_t)(cb + 5) * DH + f] = hi;
        upk(a3, lo, hi);
        if (cb + 6 < span) yb[(size_t)(cb + 6) * DH + f] = lo;
        if (cb + 7 < span) yb[(size_t)(cb + 7) * DH + f] = hi;
    }
}

// ============================================================
// SAGE aggregate: x' = relu(y[dst][:,0:64] + (sum_{src} y[src][:,64:128])/deg)
// Reads g_bufB, writes g_bufA [n][c][64].
// ============================================================
__global__ void k_sageA() {
    const int n = blockIdx.y, c0 = blockIdx.x * CT;
    const int span = min(CT, NC - c0);
    const int o0 = g_off[n], o1 = g_off[n + 1];
    const float inv = g_invdeg[n];
    const int tot = span * H;
    const float* yb = g_bufB + ((size_t)n * NC + c0) * DH;
    float* xb = g_bufA + ((size_t)n * NC + c0) * H;
    for (int idx = threadIdx.x; idx < tot; idx += 256) {
        int c = idx >> 6, h = idx & 63;
        float s = 0.f;
        for (int e = o0; e < o1; e++) {
            int src = g_adj[e];
            s += g_bufB[((size_t)src * NC + c0 + c) * DH + H + h];
        }
        float v = yb[(size_t)c * DH + h] + s * inv;
        xb[idx] = fmaxf(v, 0.f);
    }
}

// ============================================================
// Pool (max + mean over 40 nodes), L2-normalize, MLP head -> out[b][c]
// ============================================================
__global__ void __launch_bounds__(256)
k_pool(const float* __restrict__ Wp1, const float* __restrict__ bp1,
       const float* __restrict__ Wp2, const float* __restrict__ bp2,
       float* __restrict__ out) {
    __shared__ float pooled[100 * 64];
    __shared__ float w1s[64 * 32];
    __shared__ float b1s[32];
    __shared__ float w2s[32];
    const int b = blockIdx.y, c0 = blockIdx.x * 100;
    const int t = threadIdx.x;
    for (int e = t; e < 64 * 32; e += 256) w1s[e] = Wp1[e];
    if (t < 32) { b1s[t] = bp1[t]; w2s[t] = Wp2[t]; }
    const float invc = g_invcnt[b];
    const float* xb = g_bufA + ((size_t)(b * 40) * NC + c0) * H;
    for (int idx = t; idx < 100 * 64; idx += 256) {
        int c = idx >> 6, h = idx & 63;
        float mx = -3.4e38f, sm_ = 0.f;
        for (int i = 0; i < 40; i++) {
            float v = xb[((size_t)i * NC + c) * H + h];
            mx = fmaxf(mx, v);
            sm_ += v;
        }
        pooled[idx] = mx + sm_ * invc;
    }
    __syncthreads();
    const int w = t >> 5, lane = t & 31;
    const float bp2v = bp2[0];
    for (int c = w; c < 100; c += 8) {
        float v0 = pooled[c * 64 + lane], v1 = pooled[c * 64 + 32 + lane];
        float ss = v0 * v0 + v1 * v1;
        #pragma unroll
        for (int m = 16; m; m >>= 1) ss += __shfl_xor_sync(0xffffffffu, ss, m);
        float inv = rsqrtf(ss);
        float dot = 0.f;
        #pragma unroll
        for (int h = 0; h < 64; h++) dot += pooled[c * 64 + h] * w1s[h * 32 + lane];
        float hj = fmaxf(b1s[lane] + inv * dot, 0.f);
        float o = hj * w2s[lane];
        #pragma unroll
        for (int m = 16; m; m >>= 1) o += __shfl_xor_sync(0xffffffffu, o, m);
        if (lane == 0) out[b * NC + c0 + c] = o + bp2v;
    }
}

// ============================================================
extern "C" void kernel_launch(void* const* d_in, const int* in_sizes, int n_in,
                              void* d_out, int out_size) {
    const float* node_feat   = (const float*)d_in[0];
    const int*   node_opcode = (const int*)d_in[1];
    const float* config_feat = (const float*)d_in[2];
    const int*   edge_index  = (const int*)d_in[3];
    const int*   batch       = (const int*)d_in[4];
    const float* op_emb      = (const float*)d_in[5];
    const float* shape_emb   = (const float*)d_in[6];
    const float* W1  = (const float*)d_in[7];
    const float* b1  = (const float*)d_in[8];
    const float* W2  = (const float*)d_in[9];
    const float* b2  = (const float*)d_in[10];
    const float* Wl0 = (const float*)d_in[11];
    const float* Wr0 = (const float*)d_in[12];
    const float* bg0 = (const float*)d_in[13];
    const float* Wl1 = (const float*)d_in[14];
    const float* Wr1 = (const float*)d_in[15];
    const float* bg1 = (const float*)d_in[16];
    const float* Wl2 = (const float*)d_in[17];
    const float* Wr2 = (const float*)d_in[18];
    const float* bg2 = (const float*)d_in[19];
    const float* Wp1 = (const float*)d_in[20];
    const float* bp1 = (const float*)d_in[21];
    const float* Wp2 = (const float*)d_in[22];
    const float* bp2 = (const float*)d_in[23];
    float* out = (float*)d_out;

    const int SM_MLP  = (DH + CF * DH + CF * PADW + DH * PADW + DH * DH) * 4;   // ~158.6 KB
    const int SM_G128 = (128 * PADW + 128 * DH + H) * 4;                        // ~133.4 KB
    const int SM_G64  = (64 * PADW + 64 * DH + H) * 4;                          // ~66.8 KB
    cudaFuncSetAttribute(k_mlp,        cudaFuncAttributeMaxDynamicSharedMemorySize, SM_MLP);
    cudaFuncSetAttribute(k_sageG<128>, cudaFuncAttributeMaxDynamicSharedMemorySize, SM_G128);
    cudaFuncSetAttribute(k_sageG<64>,  cudaFuncAttributeMaxDynamicSharedMemorySize, SM_G64);

    dim3 grid(8, NN);
    k_prep<<<1, 512>>>(edge_index, batch);
    k_base<<<NN, 128>>>(node_feat, node_opcode, op_emb, shape_emb, W1, b1);
    k_mlp<<<grid, 256, SM_MLP>>>(config_feat, batch, W1, W2, b2);

    k_sageG<128><<<grid, 256, SM_G128>>>(Wl0, Wr0, bg0);
    k_sageA<<<grid, 256>>>();
    k_sageG<64><<<grid, 256, SM_G64>>>(Wl1, Wr1, bg1);
    k_sageA<<<grid, 256>>>();
    k_sageG<64><<<grid, 256, SM_G64>>>(Wl2, Wr2, bg2);
    k_sageA<<<grid, 256>>>();

    dim3 gpool(10, NB);
    k_pool<<<gpool, 256>>>(Wp1, bp1, Wp2, bp2, out);
}

// round 3
// speedup vs baseline: 1.2950x; 1.2950x over previous
#include <cuda_runtime.h>

#define NN 400
#define NC 1000
#define NB 10
#define NE 800
#define XND 121   // 85 cont + 4 shape emb + 32 op emb
#define CF 24
#define DH 128    // 2H
#define H 64
#define CT 128    // configs per tile
#define PADW 132  // padded smem row stride (floats)

typedef unsigned long long ull_t;

// ---- scratch (module-load allocated, no cudaMalloc) ----
__device__ float g_bufA[(size_t)NN * NC * DH];  // 204.8 MB
__device__ float g_bufB[(size_t)NN * NC * DH];  // 204.8 MB
__device__ float g_base[NN * DH];
__device__ int   g_adj[NE];
__device__ int   g_off[NN + 1];
__device__ float g_invdeg[NN];
__device__ float g_invcnt[NB];

// ---- packed f32x2 helpers ----
__device__ __forceinline__ ull_t pk2(float x) {
    ull_t r; asm("mov.b64 %0, {%1, %1};" : "=l"(r) : "f"(x)); return r;
}
__device__ __forceinline__ ull_t fma2(ull_t a, ull_t b, ull_t c) {
    ull_t d; asm("fma.rn.f32x2 %0, %1, %2, %3;" : "=l"(d) : "l"(a), "l"(b), "l"(c)); return d;
}
__device__ __forceinline__ void upk(ull_t a, float& lo, float& hi) {
    asm("mov.b64 {%0, %1}, %2;" : "=f"(lo), "=f"(hi) : "l"(a));
}

// ============================================================
// Register-tiled GEMM core: out[c][f] (+bias, opt relu)
// 256 threads, tile = 128 features x 128 configs.
// Thread tile: 4 features x 16 configs (32 f32x2 accumulators).
// xT: [D][PADW] (configs contiguous), ws: [D][128], bs128: [128]
// ============================================================
template<int D, bool RELU>
__device__ __forceinline__ void gemm_rt(const float* __restrict__ xT,
                                        const float* __restrict__ ws,
                                        const float* __restrict__ bs128,
                                        float* __restrict__ outg, int span) {
    const int t  = threadIdx.x;
    const int f0 = (t & 31) * 4;
    const int c0 = (t >> 5) * 16;

    ull_t acc[4][8];
    {
        float4 bv = *(const float4*)(bs128 + f0);
        ull_t b0 = pk2(bv.x), b1 = pk2(bv.y), b2_ = pk2(bv.z), b3 = pk2(bv.w);
        #pragma unroll
        for (int p = 0; p < 8; p++) { acc[0][p] = b0; acc[1][p] = b1; acc[2][p] = b2_; acc[3][p] = b3; }
    }

    #pragma unroll 4
    for (int k = 0; k < D; k++) {
        float4 wv = *(const float4*)(ws + k * DH + f0);
        ull_t w0 = pk2(wv.x), w1 = pk2(wv.y), w2 = pk2(wv.z), w3 = pk2(wv.w);
        const ulonglong2* xr = (const ulonglong2*)(xT + k * PADW + c0);
        #pragma unroll
        for (int q = 0; q < 4; q++) {
            ulonglong2 xv = xr[q];
            acc[0][2*q]   = fma2(xv.x, w0, acc[0][2*q]);
            acc[1][2*q]   = fma2(xv.x, w1, acc[1][2*q]);
            acc[2][2*q]   = fma2(xv.x, w2, acc[2][2*q]);
            acc[3][2*q]   = fma2(xv.x, w3, acc[3][2*q]);
            acc[0][2*q+1] = fma2(xv.y, w0, acc[0][2*q+1]);
            acc[1][2*q+1] = fma2(xv.y, w1, acc[1][2*q+1]);
            acc[2][2*q+1] = fma2(xv.y, w2, acc[2][2*q+1]);
            acc[3][2*q+1] = fma2(xv.y, w3, acc[3][2*q+1]);
        }
    }

    #pragma unroll
    for (int p = 0; p < 8; p++) {
        int c = c0 + 2 * p;
        float lo0, hi0, lo1, hi1, lo2, hi2, lo3, hi3;
        upk(acc[0][p], lo0, hi0); upk(acc[1][p], lo1, hi1);
        upk(acc[2][p], lo2, hi2); upk(acc[3][p], lo3, hi3);
        if (RELU) {
            lo0 = fmaxf(lo0, 0.f); hi0 = fmaxf(hi0, 0.f);
            lo1 = fmaxf(lo1, 0.f); hi1 = fmaxf(hi1, 0.f);
            lo2 = fmaxf(lo2, 0.f); hi2 = fmaxf(hi2, 0.f);
            lo3 = fmaxf(lo3, 0.f); hi3 = fmaxf(hi3, 0.f);
        }
        if (c < span) {
            float4 v = make_float4(lo0, lo1, lo2, lo3);
            *(float4*)(outg + (size_t)c * DH + f0) = v;
        }
        if (c + 1 < span) {
            float4 v = make_float4(hi0, hi1, hi2, hi3);
            *(float4*)(outg + (size_t)(c + 1) * DH + f0) = v;
        }
    }
}

// ============================================================
// Setup: CSR by dst, degrees, per-graph node counts. One block.
// ============================================================
__global__ void k_prep(const int* __restrict__ ei, const int* __restrict__ batch) {
    __shared__ int cnt[NN];
    __shared__ int off[NN + 1];
    __shared__ int cur[NN];
    __shared__ int bc[NB];
    int t = threadIdx.x;
    for (int i = t; i < NN; i += blockDim.x) cnt[i] = 0;
    if (t < NB) bc[t] = 0;
    __syncthreads();
    for (int e = t; e < NE; e += blockDim.x) atomicAdd(&cnt[ei[NE + e]], 1);
    for (int i = t; i < NN; i += blockDim.x) atomicAdd(&bc[batch[i]], 1);
    __syncthreads();
    if (t == 0) {
        int s = 0;
        for (int i = 0; i < NN; i++) { off[i] = s; s += cnt[i]; }
        off[NN] = s;
    }
    __syncthreads();
    for (int i = t; i < NN; i += blockDim.x) {
        cur[i] = off[i];
        g_off[i] = off[i];
        g_invdeg[i] = 1.f / fmaxf((float)cnt[i], 1.f);
    }
    if (t == 0) g_off[NN] = off[NN];
    if (t < NB) g_invcnt[t] = 1.f / fmaxf((float)bc[t], 1.f);
    __syncthreads();
    for (int e = t; e < NE; e += blockDim.x) {
        int d = ei[NE + e];
        int p = atomicAdd(&cur[d], 1);
        g_adj[p] = ei[e];
    }
}

// ============================================================
// Per-node config-invariant part of layer 1:
// base[n][f] = b1[f] + xn[n] @ W1[0:121]
// ============================================================
__global__ void k_base(const float* __restrict__ node_feat, const int* __restrict__ opcode,
                       const float* __restrict__ op_emb, const float* __restrict__ shape_emb,
                       const float* __restrict__ W1, const float* __restrict__ b1) {
    __shared__ float xns[XND];
    int n = blockIdx.x, t = threadIdx.x;
    if (t < XND) {
        float v;
        if (t < 85) v = node_feat[n * 86 + t];
        else if (t < 89) { int st = (int)node_feat[n * 86 + 85]; v = shape_emb[st * 4 + (t - 85)]; }
        else v = op_emb[opcode[n] * 32 + (t - 89)];
        xns[t] = v;
    }
    __syncthreads();
    float acc = b1[t];
    #pragma unroll 11
    for (int k = 0; k < XND; k++) acc += xns[k] * W1[k * DH + t];
    g_base[n * DH + t] = acc;
}

// ============================================================
// Fused MLP: x1 = relu(base + cfg @ W1[121:145]); x2 = relu(x1 @ W2 + b2)
// -> g_bufA [n][c][128]
// ============================================================
__global__ void __launch_bounds__(256, 1)
k_mlp(const float* __restrict__ cfgf, const int* __restrict__ batch,
      const float* __restrict__ W1, const float* __restrict__ W2, const float* __restrict__ b2) {
    extern __shared__ float sm[];
    float* sb   = sm;                   // 128 (base)
    float* b2s  = sm + DH;              // 128
    float* w1t  = b2s + DH;             // 24*128
    float* cfgT = w1t + CF * DH;        // 24*132 (transposed [j][c])
    float* x1T  = cfgT + CF * PADW;     // 128*132 (transposed [k][c])
    float* w2s  = x1T + DH * PADW;      // 128*128

    const int n = blockIdx.y;
    const int c0 = blockIdx.x * CT;
    const int span = min(CT, NC - c0);
    const int t = threadIdx.x;

    if (t < DH) { sb[t] = g_base[n * DH + t]; b2s[t] = b2[t]; }
    for (int e = t; e < CF * DH; e += 256) w1t[e] = W1[XND * DH + e];
    for (int e = t; e < DH * DH; e += 256) w2s[e] = W2[e];
    const int bn = batch[n];
    const float* cb_ = cfgf + ((size_t)bn * NC + c0) * CF;
    for (int e = t; e < CF * CT; e += 256) {
        int c = e / CF, j = e - c * CF;
        cfgT[j * PADW + c] = (c < span) ? cb_[e] : 0.f;
    }
    __syncthreads();

    // Stage 1: 24-deep GEMM, store transposed to smem (old mapping)
    {
        const int f = t & 127, g = t >> 7;
        const ull_t bb1 = pk2(sb[f]);
        #pragma unroll
        for (int p0 = g * 4; p0 < 64; p0 += 8) {
            ull_t a0 = bb1, a1 = bb1, a2 = bb1, a3 = bb1;
            const int cb = 2 * p0;
            #pragma unroll
            for (int j = 0; j < CF; j++) {
                ull_t w = pk2(w1t[j * DH + f]);
                const ulonglong2* xr = (const ulonglong2*)(cfgT + j * PADW + cb);
                ulonglong2 xA = xr[0], xB = xr[1];
                a0 = fma2(xA.x, w, a0); a1 = fma2(xA.y, w, a1);
                a2 = fma2(xB.x, w, a2); a3 = fma2(xB.y, w, a3);
            }
            float lo, hi;
            float* xrow = x1T + f * PADW + cb;
            upk(a0, lo, hi); xrow[0] = fmaxf(lo, 0.f); xrow[1] = fmaxf(hi, 0.f);
            upk(a1, lo, hi); xrow[2] = fmaxf(lo, 0.f); xrow[3] = fmaxf(hi, 0.f);
            upk(a2, lo, hi); xrow[4] = fmaxf(lo, 0.f); xrow[5] = fmaxf(hi, 0.f);
            upk(a3, lo, hi); xrow[6] = fmaxf(lo, 0.f); xrow[7] = fmaxf(hi, 0.f);
        }
    }
    __syncthreads();

    // Stage 2: 128-deep register-tiled GEMM -> global
    float* outg = g_bufA + ((size_t)n * NC + c0) * DH;
    gemm_rt<DH, true>(x1T, w2s, b2s, outg, span);
}

// ============================================================
// SAGE projection: y[n][c][0:64] = x@Wl + bg (pre-relu),
//                  y[n][c][64:128] = x@Wr.  Reads g_bufA, writes g_bufB.
// ============================================================
template<int D>
__global__ void __launch_bounds__(256, 2)
k_sageG(const float* __restrict__ Wl, const float* __restrict__ Wr, const float* __restrict__ bg) {
    extern __shared__ float sm[];
    float* xT = sm;               // D*PADW
    float* ws = xT + D * PADW;    // D*128 (Wl | Wr interleaved on f)
    float* bs = ws + D * DH;      // 128 (bg | zeros)
    const int n = blockIdx.y, c0 = blockIdx.x * CT;
    const int span = min(CT, NC - c0);
    const int t = threadIdx.x;

    if (t < DH) bs[t] = (t < H) ? bg[t] : 0.f;
    for (int e = t; e < D * H; e += 256) {
        int k = e / H, f = e - k * H;
        ws[k * DH + f]     = Wl[e];
        ws[k * DH + H + f] = Wr[e];
    }
    const float* xb = g_bufA + ((size_t)n * NC + c0) * D;
    for (int e = t; e < D * CT; e += 256) {
        int c = e / D, k = e - c * D;
        xT[k * PADW + c] = (c < span) ? xb[e] : 0.f;
    }
    __syncthreads();

    float* yb = g_bufB + ((size_t)n * NC + c0) * DH;
    gemm_rt<D, false>(xT, ws, bs, yb, span);
}

// ============================================================
// SAGE aggregate: x' = relu(y[dst][:,0:64] + (sum_{src} y[src][:,64:128])/deg)
// Reads g_bufB, writes g_bufA [n][c][64].
// ============================================================
__global__ void k_sageA() {
    const int n = blockIdx.y, c0 = blockIdx.x * CT;
    const int span = min(CT, NC - c0);
    const int o0 = g_off[n], o1 = g_off[n + 1];
    const float inv = g_invdeg[n];
    const int tot = span * H;
    const float* yb = g_bufB + ((size_t)n * NC + c0) * DH;
    float* xb = g_bufA + ((size_t)n * NC + c0) * H;
    for (int idx = threadIdx.x; idx < tot; idx += 256) {
        int c = idx >> 6, h = idx & 63;
        float s = 0.f;
        for (int e = o0; e < o1; e++) {
            int src = g_adj[e];
            s += g_bufB[((size_t)src * NC + c0 + c) * DH + H + h];
        }
        float v = yb[(size_t)c * DH + h] + s * inv;
        xb[idx] = fmaxf(v, 0.f);
    }
}

// ============================================================
// Pool (max + mean over 40 nodes), L2-normalize, MLP head -> out[b][c]
// ============================================================
__global__ void __launch_bounds__(256)
k_pool(const float* __restrict__ Wp1, const float* __restrict__ bp1,
       const float* __restrict__ Wp2, const float* __restrict__ bp2,
       float* __restrict__ out) {
    __shared__ float pooled[100 * 64];
    __shared__ float w1s[64 * 32];
    __shared__ float b1s[32];
    __shared__ float w2s[32];
    const int b = blockIdx.y, c0 = blockIdx.x * 100;
    const int t = threadIdx.x;
    for (int e = t; e < 64 * 32; e += 256) w1s[e] = Wp1[e];
    if (t < 32) { b1s[t] = bp1[t]; w2s[t] = Wp2[t]; }
    const float invc = g_invcnt[b];
    const float* xb = g_bufA + ((size_t)(b * 40) * NC + c0) * H;
    for (int idx = t; idx < 100 * 64; idx += 256) {
        int c = idx >> 6, h = idx & 63;
        float mx = -3.4e38f, sm_ = 0.f;
        for (int i = 0; i < 40; i++) {
            float v = xb[((size_t)i * NC + c) * H + h];
            mx = fmaxf(mx, v);
            sm_ += v;
        }
        pooled[idx] = mx + sm_ * invc;
    }
    __syncthreads();
    const int w = t >> 5, lane = t & 31;
    const float bp2v = bp2[0];
    for (int c = w; c < 100; c += 8) {
        float v0 = pooled[c * 64 + lane], v1 = pooled[c * 64 + 32 + lane];
        float ss = v0 * v0 + v1 * v1;
        #pragma unroll
        for (int m = 16; m; m >>= 1) ss += __shfl_xor_sync(0xffffffffu, ss, m);
        float inv = rsqrtf(ss);
        float dot = 0.f;
        #pragma unroll
        for (int h = 0; h < 64; h++) dot += pooled[c * 64 + h] * w1s[h * 32 + lane];
        float hj = fmaxf(b1s[lane] + inv * dot, 0.f);
        float o = hj * w2s[lane];
        #pragma unroll
        for (int m = 16; m; m >>= 1) o += __shfl_xor_sync(0xffffffffu, o, m);
        if (lane == 0) out[b * NC + c0 + c] = o + bp2v;
    }
}

// ============================================================
extern "C" void kernel_launch(void* const* d_in, const int* in_sizes, int n_in,
                              void* d_out, int out_size) {
    const float* node_feat   = (const float*)d_in[0];
    const int*   node_opcode = (const int*)d_in[1];
    const float* config_feat = (const float*)d_in[2];
    const int*   edge_index  = (const int*)d_in[3];
    const int*   batch       = (const int*)d_in[4];
    const float* op_emb      = (const float*)d_in[5];
    const float* shape_emb   = (const float*)d_in[6];
    const float* W1  = (const float*)d_in[7];
    const float* b1  = (const float*)d_in[8];
    const float* W2  = (const float*)d_in[9];
    const float* b2  = (const float*)d_in[10];
    const float* Wl0 = (const float*)d_in[11];
    const float* Wr0 = (const float*)d_in[12];
    const float* bg0 = (const float*)d_in[13];
    const float* Wl1 = (const float*)d_in[14];
    const float* Wr1 = (const float*)d_in[15];
    const float* bg1 = (const float*)d_in[16];
    const float* Wl2 = (const float*)d_in[17];
    const float* Wr2 = (const float*)d_in[18];
    const float* bg2 = (const float*)d_in[19];
    const float* Wp1 = (const float*)d_in[20];
    const float* bp1 = (const float*)d_in[21];
    const float* Wp2 = (const float*)d_in[22];
    const float* bp2 = (const float*)d_in[23];
    float* out = (float*)d_out;

    const int SM_MLP  = (2 * DH + CF * DH + CF * PADW + DH * PADW + DH * DH) * 4; // ~159 KB
    const int SM_G128 = (128 * PADW + 128 * DH + DH) * 4;                          // ~134 KB
    const int SM_G64  = (64 * PADW + 64 * DH + DH) * 4;                            // ~67 KB
    cudaFuncSetAttribute(k_mlp,        cudaFuncAttributeMaxDynamicSharedMemorySize, SM_MLP);
    cudaFuncSetAttribute(k_sageG<128>, cudaFuncAttributeMaxDynamicSharedMemorySize, SM_G128);
    cudaFuncSetAttribute(k_sageG<64>,  cudaFuncAttributeMaxDynamicSharedMemorySize, SM_G64);

    dim3 grid(8, NN);
    k_prep<<<1, 512>>>(edge_index, batch);
    k_base<<<NN, 128>>>(node_feat, node_opcode, op_emb, shape_emb, W1, b1);
    k_mlp<<<grid, 256, SM_MLP>>>(config_feat, batch, W1, W2, b2);

    k_sageG<128><<<grid, 256, SM_G128>>>(Wl0, Wr0, bg0);
    k_sageA<<<grid, 256>>>();
    k_sageG<64><<<grid, 256, SM_G64>>>(Wl1, Wr1, bg1);
    k_sageA<<<grid, 256>>>();
    k_sageG<64><<<grid, 256, SM_G64>>>(Wl2, Wr2, bg2);
    k_sageA<<<grid, 256>>>();

    dim3 gpool(10, NB);
    k_pool<<<gpool, 256>>>(Wp1, bp1, Wp2, bp2, out);
}

// round 4
// speedup vs baseline: 1.4289x; 1.1034x over previous
#include <cuda_runtime.h>

#define NN 400
#define NC 1000
#define NB 10
#define NE 800
#define XND 121   // 85 cont + 4 shape emb + 32 op emb
#define CF 24
#define DH 128    // 2H
#define H 64
#define CT 128    // configs per tile
#define PADW 132  // padded smem row stride (floats)

typedef unsigned long long ull_t;

// ---- scratch (module-load allocated, no cudaMalloc) ----
__device__ float g_bufA[(size_t)NN * NC * DH];  // 204.8 MB
__device__ float g_bufB[(size_t)NN * NC * DH];  // 204.8 MB
__device__ float g_base[NN * DH];
__device__ int   g_adj[NE];
__device__ int   g_off[NN + 1];
__device__ float g_invdeg[NN];
__device__ float g_invcnt[NB];

// ---- packed f32x2 helpers ----
__device__ __forceinline__ ull_t pk2(float x) {
    ull_t r; asm("mov.b64 %0, {%1, %1};" : "=l"(r) : "f"(x)); return r;
}
__device__ __forceinline__ ull_t fma2(ull_t a, ull_t b, ull_t c) {
    ull_t d; asm("fma.rn.f32x2 %0, %1, %2, %3;" : "=l"(d) : "l"(a), "l"(b), "l"(c)); return d;
}
__device__ __forceinline__ void upk(ull_t a, float& lo, float& hi) {
    asm("mov.b64 {%0, %1}, %2;" : "=f"(lo), "=f"(hi) : "l"(a));
}

// ============================================================
// Register-tiled GEMM core, 512 threads: tile = 128f x 128c.
// Thread tile: 4 features x 8 configs (16 f32x2 accumulators).
// Warp-uniform c0 -> x loads are smem broadcasts.
// xT: [D][PADW] (configs contiguous), ws: [D][128], bs128: [128]
// ============================================================
template<int D, bool RELU>
__device__ __forceinline__ void gemm_rt512(const float* __restrict__ xT,
                                           const float* __restrict__ ws,
                                           const float* __restrict__ bs128,
                                           float* __restrict__ outg, int span) {
    const int t  = threadIdx.x;
    const int f0 = (t & 31) * 4;
    const int c0 = (t >> 5) * 8;

    ull_t acc[4][4];
    {
        float4 bv = *(const float4*)(bs128 + f0);
        ull_t b0 = pk2(bv.x), b1 = pk2(bv.y), b2_ = pk2(bv.z), b3 = pk2(bv.w);
        #pragma unroll
        for (int p = 0; p < 4; p++) { acc[0][p] = b0; acc[1][p] = b1; acc[2][p] = b2_; acc[3][p] = b3; }
    }

    #pragma unroll 4
    for (int k = 0; k < D; k++) {
        float4 wv = *(const float4*)(ws + k * DH + f0);
        ull_t w0 = pk2(wv.x), w1 = pk2(wv.y), w2 = pk2(wv.z), w3 = pk2(wv.w);
        const ulonglong2* xr = (const ulonglong2*)(xT + k * PADW + c0);
        ulonglong2 xA = xr[0], xB = xr[1];
        acc[0][0] = fma2(xA.x, w0, acc[0][0]);
        acc[1][0] = fma2(xA.x, w1, acc[1][0]);
        acc[2][0] = fma2(xA.x, w2, acc[2][0]);
        acc[3][0] = fma2(xA.x, w3, acc[3][0]);
        acc[0][1] = fma2(xA.y, w0, acc[0][1]);
        acc[1][1] = fma2(xA.y, w1, acc[1][1]);
        acc[2][1] = fma2(xA.y, w2, acc[2][1]);
        acc[3][1] = fma2(xA.y, w3, acc[3][1]);
        acc[0][2] = fma2(xB.x, w0, acc[0][2]);
        acc[1][2] = fma2(xB.x, w1, acc[1][2]);
        acc[2][2] = fma2(xB.x, w2, acc[2][2]);
        acc[3][2] = fma2(xB.x, w3, acc[3][2]);
        acc[0][3] = fma2(xB.y, w0, acc[0][3]);
        acc[1][3] = fma2(xB.y, w1, acc[1][3]);
        acc[2][3] = fma2(xB.y, w2, acc[2][3]);
        acc[3][3] = fma2(xB.y, w3, acc[3][3]);
    }

    #pragma unroll
    for (int p = 0; p < 4; p++) {
        int c = c0 + 2 * p;
        float lo0, hi0, lo1, hi1, lo2, hi2, lo3, hi3;
        upk(acc[0][p], lo0, hi0); upk(acc[1][p], lo1, hi1);
        upk(acc[2][p], lo2, hi2); upk(acc[3][p], lo3, hi3);
        if (RELU) {
            lo0 = fmaxf(lo0, 0.f); hi0 = fmaxf(hi0, 0.f);
            lo1 = fmaxf(lo1, 0.f); hi1 = fmaxf(hi1, 0.f);
            lo2 = fmaxf(lo2, 0.f); hi2 = fmaxf(hi2, 0.f);
            lo3 = fmaxf(lo3, 0.f); hi3 = fmaxf(hi3, 0.f);
        }
        if (c < span) {
            float4 v = make_float4(lo0, lo1, lo2, lo3);
            *(float4*)(outg + (size_t)c * DH + f0) = v;
        }
        if (c + 1 < span) {
            float4 v = make_float4(hi0, hi1, hi2, hi3);
            *(float4*)(outg + (size_t)(c + 1) * DH + f0) = v;
        }
    }
}

// ============================================================
// Setup: CSR by dst, degrees, per-graph node counts. One block.
// ============================================================
__global__ void k_prep(const int* __restrict__ ei, const int* __restrict__ batch) {
    __shared__ int cnt[NN];
    __shared__ int off[NN + 1];
    __shared__ int cur[NN];
    __shared__ int bc[NB];
    int t = threadIdx.x;
    for (int i = t; i < NN; i += blockDim.x) cnt[i] = 0;
    if (t < NB) bc[t] = 0;
    __syncthreads();
    for (int e = t; e < NE; e += blockDim.x) atomicAdd(&cnt[ei[NE + e]], 1);
    for (int i = t; i < NN; i += blockDim.x) atomicAdd(&bc[batch[i]], 1);
    __syncthreads();
    if (t == 0) {
        int s = 0;
        for (int i = 0; i < NN; i++) { off[i] = s; s += cnt[i]; }
        off[NN] = s;
    }
    __syncthreads();
    for (int i = t; i < NN; i += blockDim.x) {
        cur[i] = off[i];
        g_off[i] = off[i];
        g_invdeg[i] = 1.f / fmaxf((float)cnt[i], 1.f);
    }
    if (t == 0) g_off[NN] = off[NN];
    if (t < NB) g_invcnt[t] = 1.f / fmaxf((float)bc[t], 1.f);
    __syncthreads();
    for (int e = t; e < NE; e += blockDim.x) {
        int d = ei[NE + e];
        int p = atomicAdd(&cur[d], 1);
        g_adj[p] = ei[e];
    }
}

// ============================================================
// Per-node config-invariant part of layer 1:
// base[n][f] = b1[f] + xn[n] @ W1[0:121]
// ============================================================
__global__ void k_base(const float* __restrict__ node_feat, const int* __restrict__ opcode,
                       const float* __restrict__ op_emb, const float* __restrict__ shape_emb,
                       const float* __restrict__ W1, const float* __restrict__ b1) {
    __shared__ float xns[XND];
    int n = blockIdx.x, t = threadIdx.x;
    if (t < XND) {
        float v;
        if (t < 85) v = node_feat[n * 86 + t];
        else if (t < 89) { int st = (int)node_feat[n * 86 + 85]; v = shape_emb[st * 4 + (t - 85)]; }
        else v = op_emb[opcode[n] * 32 + (t - 89)];
        xns[t] = v;
    }
    __syncthreads();
    float acc = b1[t];
    #pragma unroll 11
    for (int k = 0; k < XND; k++) acc += xns[k] * W1[k * DH + t];
    g_base[n * DH + t] = acc;
}

// ============================================================
// Fused MLP: x1 = relu(base + cfg @ W1[121:145]); x2 = relu(x1 @ W2 + b2)
// -> g_bufA [n][c][128].  512 threads.
// ============================================================
__global__ void __launch_bounds__(512, 1)
k_mlp(const float* __restrict__ cfgf, const int* __restrict__ batch,
      const float* __restrict__ W1, const float* __restrict__ W2, const float* __restrict__ b2) {
    extern __shared__ float sm[];
    float* sb   = sm;                   // 128 (base)
    float* b2s  = sm + DH;              // 128
    float* w1t  = b2s + DH;             // 24*128
    float* cfgT = w1t + CF * DH;        // 24*132 (transposed [j][c])
    float* x1T  = cfgT + CF * PADW;     // 128*132 (transposed [k][c])
    float* w2s  = x1T + DH * PADW;      // 128*128

    const int n = blockIdx.y;
    const int c0 = blockIdx.x * CT;
    const int span = min(CT, NC - c0);
    const int t = threadIdx.x;

    if (t < DH) { sb[t] = g_base[n * DH + t]; b2s[t] = b2[t]; }
    for (int e = t; e < CF * DH; e += 512) w1t[e] = W1[XND * DH + e];
    for (int e = t; e < DH * DH; e += 512) w2s[e] = W2[e];
    const int bn = batch[n];
    const float* cb_ = cfgf + ((size_t)bn * NC + c0) * CF;
    for (int e = t; e < CF * CT; e += 512) {
        int c = e / CF, j = e - c * CF;
        cfgT[j * PADW + c] = (c < span) ? cb_[e] : 0.f;
    }
    __syncthreads();

    // Stage 1: 24-deep GEMM, store transposed to smem
    {
        const int f = t & 127, g = t >> 7;  // g in 0..3
        const ull_t bb1 = pk2(sb[f]);
        #pragma unroll
        for (int p0 = g * 4; p0 < 64; p0 += 16) {
            ull_t a0 = bb1, a1 = bb1, a2 = bb1, a3 = bb1;
            const int cb = 2 * p0;
            #pragma unroll
            for (int j = 0; j < CF; j++) {
                ull_t w = pk2(w1t[j * DH + f]);
                const ulonglong2* xr = (const ulonglong2*)(cfgT + j * PADW + cb);
                ulonglong2 xA = xr[0], xB = xr[1];
                a0 = fma2(xA.x, w, a0); a1 = fma2(xA.y, w, a1);
                a2 = fma2(xB.x, w, a2); a3 = fma2(xB.y, w, a3);
            }
            float lo, hi;
            float* xrow = x1T + f * PADW + cb;
            upk(a0, lo, hi); xrow[0] = fmaxf(lo, 0.f); xrow[1] = fmaxf(hi, 0.f);
            upk(a1, lo, hi); xrow[2] = fmaxf(lo, 0.f); xrow[3] = fmaxf(hi, 0.f);
            upk(a2, lo, hi); xrow[4] = fmaxf(lo, 0.f); xrow[5] = fmaxf(hi, 0.f);
            upk(a3, lo, hi); xrow[6] = fmaxf(lo, 0.f); xrow[7] = fmaxf(hi, 0.f);
        }
    }
    __syncthreads();

    // Stage 2: 128-deep register-tiled GEMM -> global
    float* outg = g_bufA + ((size_t)n * NC + c0) * DH;
    gemm_rt512<DH, true>(x1T, w2s, b2s, outg, span);
}

// ============================================================
// SAGE projection (D=128 input): 512 threads, 1 CTA/SM.
// y[n][c][0:64] = x@Wl + bg (pre-relu), y[n][c][64:128] = x@Wr.
// ============================================================
__global__ void __launch_bounds__(512, 1)
k_sageG128(const float* __restrict__ Wl, const float* __restrict__ Wr, const float* __restrict__ bg) {
    extern __shared__ float sm[];
    float* xT = sm;                  // 128*PADW
    float* ws = xT + 128 * PADW;     // 128*128 (Wl | Wr interleaved on f)
    float* bs = ws + 128 * DH;       // 128 (bg | zeros)
    const int n = blockIdx.y, c0 = blockIdx.x * CT;
    const int span = min(CT, NC - c0);
    const int t = threadIdx.x;

    if (t < DH) bs[t] = (t < H) ? bg[t] : 0.f;
    for (int e = t; e < 128 * H; e += 512) {
        int k = e / H, f = e - k * H;
        ws[k * DH + f]     = Wl[e];
        ws[k * DH + H + f] = Wr[e];
    }
    const float* xb = g_bufA + ((size_t)n * NC + c0) * 128;
    for (int e = t; e < 128 * CT; e += 512) {
        int c = e >> 7, k = e & 127;
        xT[k * PADW + c] = (c < span) ? xb[e] : 0.f;
    }
    __syncthreads();

    float* yb = g_bufB + ((size_t)n * NC + c0) * DH;
    gemm_rt512<128, false>(xT, ws, bs, yb, span);
}

// ============================================================
// SAGE projection (D=64 input): 256 threads, 2 CTAs/SM (R2 layout).
// ============================================================
__global__ void __launch_bounds__(256, 2)
k_sageG64(const float* __restrict__ Wl, const float* __restrict__ Wr, const float* __restrict__ bg) {
    extern __shared__ float sm[];
    float* xT = sm;                // 64*PADW
    float* ws = xT + 64 * PADW;    // 64*128
    float* bs = ws + 64 * DH;      // 128
    const int n = blockIdx.y, c0 = blockIdx.x * CT;
    const int span = min(CT, NC - c0);
    const int t = threadIdx.x;

    if (t < DH) bs[t] = (t < H) ? bg[t] : 0.f;
    for (int e = t; e < 64 * H; e += 256) {
        int k = e / H, f = e - k * H;
        ws[k * DH + f]     = Wl[e];
        ws[k * DH + H + f] = Wr[e];
    }
    const float* xb = g_bufA + ((size_t)n * NC + c0) * 64;
    for (int e = t; e < 64 * CT; e += 256) {
        int c = e >> 6, k = e & 63;
        xT[k * PADW + c] = (c < span) ? xb[e] : 0.f;
    }
    __syncthreads();

    // 256-thread register tile: 4f x 16c
    const int f0 = (t & 31) * 4;
    const int c0t = (t >> 5) * 16;
    ull_t acc[4][8];
    {
        float4 bv = *(const float4*)(bs + f0);
        ull_t b0 = pk2(bv.x), b1 = pk2(bv.y), b2_ = pk2(bv.z), b3 = pk2(bv.w);
        #pragma unroll
        for (int p = 0; p < 8; p++) { acc[0][p] = b0; acc[1][p] = b1; acc[2][p] = b2_; acc[3][p] = b3; }
    }
    #pragma unroll 4
    for (int k = 0; k < 64; k++) {
        float4 wv = *(const float4*)(ws + k * DH + f0);
        ull_t w0 = pk2(wv.x), w1 = pk2(wv.y), w2 = pk2(wv.z), w3 = pk2(wv.w);
        const ulonglong2* xr = (const ulonglong2*)(xT + k * PADW + c0t);
        #pragma unroll
        for (int q = 0; q < 4; q++) {
            ulonglong2 xv = xr[q];
            acc[0][2*q]   = fma2(xv.x, w0, acc[0][2*q]);
            acc[1][2*q]   = fma2(xv.x, w1, acc[1][2*q]);
            acc[2][2*q]   = fma2(xv.x, w2, acc[2][2*q]);
            acc[3][2*q]   = fma2(xv.x, w3, acc[3][2*q]);
            acc[0][2*q+1] = fma2(xv.y, w0, acc[0][2*q+1]);
            acc[1][2*q+1] = fma2(xv.y, w1, acc[1][2*q+1]);
            acc[2][2*q+1] = fma2(xv.y, w2, acc[2][2*q+1]);
            acc[3][2*q+1] = fma2(xv.y, w3, acc[3][2*q+1]);
        }
    }
    float* yb = g_bufB + ((size_t)n * NC + c0) * DH;
    #pragma unroll
    for (int p = 0; p < 8; p++) {
        int c = c0t + 2 * p;
        float lo0, hi0, lo1, hi1, lo2, hi2, lo3, hi3;
        upk(acc[0][p], lo0, hi0); upk(acc[1][p], lo1, hi1);
        upk(acc[2][p], lo2, hi2); upk(acc[3][p], lo3, hi3);
        if (c < span)     *(float4*)(yb + (size_t)c * DH + f0)       = make_float4(lo0, lo1, lo2, lo3);
        if (c + 1 < span) *(float4*)(yb + (size_t)(c + 1) * DH + f0) = make_float4(hi0, hi1, hi2, hi3);
    }
}

// ============================================================
// SAGE aggregate: x' = relu(y[dst][:,0:64] + (sum_{src} y[src][:,64:128])/deg)
// Reads g_bufB, writes g_bufA [n][c][64].
// ============================================================
__global__ void k_sageA() {
    const int n = blockIdx.y, c0 = blockIdx.x * CT;
    const int span = min(CT, NC - c0);
    const int o0 = g_off[n], o1 = g_off[n + 1];
    const float inv = g_invdeg[n];
    const int tot = span * H;
    const float* yb = g_bufB + ((size_t)n * NC + c0) * DH;
    float* xb = g_bufA + ((size_t)n * NC + c0) * H;
    for (int idx = threadIdx.x; idx < tot; idx += 256) {
        int c = idx >> 6, h = idx & 63;
        float s = 0.f;
        for (int e = o0; e < o1; e++) {
            int src = g_adj[e];
            s += g_bufB[((size_t)src * NC + c0 + c) * DH + H + h];
        }
        float v = yb[(size_t)c * DH + h] + s * inv;
        xb[idx] = fmaxf(v, 0.f);
    }
}

// ============================================================
// Pool (max + mean over 40 nodes), L2-normalize, MLP head -> out[b][c]
// ============================================================
__global__ void __launch_bounds__(256)
k_pool(const float* __restrict__ Wp1, const float* __restrict__ bp1,
       const float* __restrict__ Wp2, const float* __restrict__ bp2,
       float* __restrict__ out) {
    __shared__ float pooled[100 * 64];
    __shared__ float w1s[64 * 32];
    __shared__ float b1s[32];
    __shared__ float w2s[32];
    const int b = blockIdx.y, c0 = blockIdx.x * 100;
    const int t = threadIdx.x;
    for (int e = t; e < 64 * 32; e += 256) w1s[e] = Wp1[e];
    if (t < 32) { b1s[t] = bp1[t]; w2s[t] = Wp2[t]; }
    const float invc = g_invcnt[b];
    const float* xb = g_bufA + ((size_t)(b * 40) * NC + c0) * H;
    for (int idx = t; idx < 100 * 64; idx += 256) {
        int c = idx >> 6, h = idx & 63;
        float mx = -3.4e38f, sm_ = 0.f;
        for (int i = 0; i < 40; i++) {
            float v = xb[((size_t)i * NC + c) * H + h];
            mx = fmaxf(mx, v);
            sm_ += v;
        }
        pooled[idx] = mx + sm_ * invc;
    }
    __syncthreads();
    const int w = t >> 5, lane = t & 31;
    const float bp2v = bp2[0];
    for (int c = w; c < 100; c += 8) {
        float v0 = pooled[c * 64 + lane], v1 = pooled[c * 64 + 32 + lane];
        float ss = v0 * v0 + v1 * v1;
        #pragma unroll
        for (int m = 16; m; m >>= 1) ss += __shfl_xor_sync(0xffffffffu, ss, m);
        float inv = rsqrtf(ss);
        float dot = 0.f;
        #pragma unroll
        for (int h = 0; h < 64; h++) dot += pooled[c * 64 + h] * w1s[h * 32 + lane];
        float hj = fmaxf(b1s[lane] + inv * dot, 0.f);
        float o = hj * w2s[lane];
        #pragma unroll
        for (int m = 16; m; m >>= 1) o += __shfl_xor_sync(0xffffffffu, o, m);
        if (lane == 0) out[b * NC + c0 + c] = o + bp2v;
    }
}

// ============================================================
extern "C" void kernel_launch(void* const* d_in, const int* in_sizes, int n_in,
                              void* d_out, int out_size) {
    const float* node_feat   = (const float*)d_in[0];
    const int*   node_opcode = (const int*)d_in[1];
    const float* config_feat = (const float*)d_in[2];
    const int*   edge_index  = (const int*)d_in[3];
    const int*   batch       = (const int*)d_in[4];
    const float* op_emb      = (const float*)d_in[5];
    const float* shape_emb   = (const float*)d_in[6];
    const float* W1  = (const float*)d_in[7];
    const float* b1  = (const float*)d_in[8];
    const float* W2  = (const float*)d_in[9];
    const float* b2  = (const float*)d_in[10];
    const float* Wl0 = (const float*)d_in[11];
    const float* Wr0 = (const float*)d_in[12];
    const float* bg0 = (const float*)d_in[13];
    const float* Wl1 = (const float*)d_in[14];
    const float* Wr1 = (const float*)d_in[15];
    const float* bg1 = (const float*)d_in[16];
    const float* Wl2 = (const float*)d_in[17];
    const float* Wr2 = (const float*)d_in[18];
    const float* bg2 = (const float*)d_in[19];
    const float* Wp1 = (const float*)d_in[20];
    const float* bp1 = (const float*)d_in[21];
    const float* Wp2 = (const float*)d_in[22];
    const float* bp2 = (const float*)d_in[23];
    float* out = (float*)d_out;

    const int SM_MLP  = (2 * DH + CF * DH + CF * PADW + DH * PADW + DH * DH) * 4; // ~159 KB
    const int SM_G128 = (128 * PADW + 128 * DH + DH) * 4;                          // ~134 KB
    const int SM_G64  = (64 * PADW + 64 * DH + DH) * 4;                            // ~67 KB
    cudaFuncSetAttribute(k_mlp,      cudaFuncAttributeMaxDynamicSharedMemorySize, SM_MLP);
    cudaFuncSetAttribute(k_sageG128, cudaFuncAttributeMaxDynamicSharedMemorySize, SM_G128);
    cudaFuncSetAttribute(k_sageG64,  cudaFuncAttributeMaxDynamicSharedMemorySize, SM_G64);

    dim3 grid(8, NN);
    k_prep<<<1, 512>>>(edge_index, batch);
    k_base<<<NN, 128>>>(node_feat, node_opcode, op_emb, shape_emb, W1, b1);
    k_mlp<<<grid, 512, SM_MLP>>>(config_feat, batch, W1, W2, b2);

    k_sageG128<<<grid, 512, SM_G128>>>(Wl0, Wr0, bg0);
    k_sageA<<<grid, 256>>>();
    k_sageG64<<<grid, 256, SM_G64>>>(Wl1, Wr1, bg1);
    k_sageA<<<grid, 256>>>();
    k_sageG64<<<grid, 256, SM_G64>>>(Wl2, Wr2, bg2);
    k_sageA<<<grid, 256>>>();

    dim3 gpool(10, NB);
    k_pool<<<gpool, 256>>>(Wp1, bp1, Wp2, bp2, out);
}